// round 16
// baseline (speedup 1.0000x reference)
#include <cuda_runtime.h>

// Persistent grid-stride variant: exactly one wave (148 SMs x 8 CTAs = 1184
// blocks), eliminating (n_waves-1) wave transitions / per-wave DRAM
// ramp-drain of the 16384-CTA launch. Inner geometry unchanged from the
// measured optimum: 4x block-strided rows per thread per iteration
// (warp-coalesced LDG/STG.128, MLP_p1=4), __ldcs/__stcs streaming,
// half-angle identity (one MUFU/row, s2+c2=1 exact).
#define THREADS 256
#define CTAS    1184   // 148 SMs * 8 resident CTAs (8 warps each = 64 warps/SM)

__global__ void __launch_bounds__(THREADS)
quantum_probs_persist(const float4* __restrict__ in,
                      float4* __restrict__ out,
                      int n) {
    const int tid = threadIdx.x;
    const int chunk = THREADS * 4;                  // rows per CTA per iteration
    const int step = gridDim.x * chunk;             // rows per grid iteration

    for (int base = blockIdx.x * chunk + tid; base < n; base += step) {
        int i0 = base;
        int i1 = base + THREADS;
        int i2 = base + 2 * THREADS;
        int i3 = base + 3 * THREADS;

        if (i3 < n) {
            float4 r0 = __ldcs(&in[i0]);
            float4 r1 = __ldcs(&in[i1]);
            float4 r2 = __ldcs(&in[i2]);
            float4 r3 = __ldcs(&in[i3]);

            float t0 = __cosf(r0.x);
            float t1 = __cosf(r1.x);
            float t2 = __cosf(r2.x);
            float t3 = __cosf(r3.x);

            float c20 = fmaf(0.5f, t0, 0.5f), s20 = fmaf(-0.5f, t0, 0.5f);
            float c21 = fmaf(0.5f, t1, 0.5f), s21 = fmaf(-0.5f, t1, 0.5f);
            float c22 = fmaf(0.5f, t2, 0.5f), s22 = fmaf(-0.5f, t2, 0.5f);
            float c23 = fmaf(0.5f, t3, 0.5f), s23 = fmaf(-0.5f, t3, 0.5f);

            __stcs(&out[i0], make_float4(c20 * c20, c20 * s20, s20 * s20, s20 * c20));
            __stcs(&out[i1], make_float4(c21 * c21, c21 * s21, s21 * s21, s21 * c21));
            __stcs(&out[i2], make_float4(c22 * c22, c22 * s22, s22 * s22, s22 * c22));
            __stcs(&out[i3], make_float4(c23 * c23, c23 * s23, s23 * s23, s23 * c23));
        } else {
            // Ragged final chunk (N=16M / 1,212,416 rows-per-iter is not integral)
            for (int i = i0; i < n; i += THREADS) {
                float4 rr = __ldcs(&in[i]);
                float t = __cosf(rr.x);
                float c2 = fmaf(0.5f, t, 0.5f);
                float s2 = fmaf(-0.5f, t, 0.5f);
                __stcs(&out[i], make_float4(c2 * c2, c2 * s2, s2 * s2, s2 * c2));
            }
        }
    }
}

extern "C" void kernel_launch(void* const* d_in, const int* in_sizes, int n_in,
                              void* d_out, int out_size) {
    const float4* in = (const float4*)d_in[0];
    float4* out = (float4*)d_out;
    int n = in_sizes[0] / 4;                  // N rows
    quantum_probs_persist<<<CTAS, THREADS>>>(in, out, n);
}

// round 17
// speedup vs baseline: 1.1249x; 1.1249x over previous
#include <cuda_runtime.h>

// TERMINAL KERNEL (reverted to R9 config after the persistent-grid experiment
// regressed: ncu 73.95 -> 79.30us, DRAM 82 -> 77%. Classic launches overlap
// "waves" for free via GigaThread backfill; a grid-stride loop serializes
// memory batches behind loop-carried control with no independent-CTA pool to
// cover the gaps.)
//
// HBM-roofline-bound: ~6.5 TB/s (81-82% of spec) for this irreducible
// interleaved 256MB-read + 256MB-write stream. Traffic provably minimal
// (col-0 at 16B pitch demands every 32B input sector; output fully written,
// full-sector STG.128). Levers tested and closed: MLP {1,4,8}, consecutive
// vs block-strided, 128/256 threads, cache hints, sincos vs half-angle,
// classic vs persistent grid. Compute pipes <5% busy.
//
//  - 4x block-strided rows/thread: every LDG/STG.128 warp-coalesced
//    (contiguous 512B per instruction), 4 independent front-batched loads
//    (MLP_p1=4, measured optimum).
//  - __ldcs/__stcs: evict-first; zero-reuse stream keeps L2 clean.
//  - Half-angle identity: cos^2(t/2) = 0.5 + 0.5*cos(t),
//    sin^2(t/2) = 0.5 - 0.5*cos(t) -> one MUFU per row, short dep chain,
//    exact complement. rel_err 1.45e-7.
__global__ void __launch_bounds__(256)
quantum_probs_final(const float4* __restrict__ in,
                    float4* __restrict__ out,
                    int n) {
    const int tid = threadIdx.x;
    const int stride = blockDim.x;
    const int base = blockIdx.x * (stride * 4) + tid;

    if (base + 3 * stride < n) {
        float4 r0 = __ldcs(&in[base + 0 * stride]);
        float4 r1 = __ldcs(&in[base + 1 * stride]);
        float4 r2 = __ldcs(&in[base + 2 * stride]);
        float4 r3 = __ldcs(&in[base + 3 * stride]);

        float t0 = __cosf(r0.x);
        float t1 = __cosf(r1.x);
        float t2 = __cosf(r2.x);
        float t3 = __cosf(r3.x);

        float c20 = fmaf(0.5f, t0, 0.5f), s20 = fmaf(-0.5f, t0, 0.5f);
        float c21 = fmaf(0.5f, t1, 0.5f), s21 = fmaf(-0.5f, t1, 0.5f);
        float c22 = fmaf(0.5f, t2, 0.5f), s22 = fmaf(-0.5f, t2, 0.5f);
        float c23 = fmaf(0.5f, t3, 0.5f), s23 = fmaf(-0.5f, t3, 0.5f);

        __stcs(&out[base + 0 * stride], make_float4(c20 * c20, c20 * s20, s20 * s20, s20 * c20));
        __stcs(&out[base + 1 * stride], make_float4(c21 * c21, c21 * s21, s21 * s21, s21 * c21));
        __stcs(&out[base + 2 * stride], make_float4(c22 * c22, c22 * s22, s22 * s22, s22 * c22));
        __stcs(&out[base + 3 * stride], make_float4(c23 * c23, c23 * s23, s23 * s23, s23 * c23));
    } else {
        // Tail path (not taken for N = 16M: 1024 rows/block divides N)
        for (int i = base; i < n; i += stride) {
            float4 rr = __ldcs(&in[i]);
            float t = __cosf(rr.x);
            float c2 = fmaf(0.5f, t, 0.5f);
            float s2 = fmaf(-0.5f, t, 0.5f);
            __stcs(&out[i], make_float4(c2 * c2, c2 * s2, s2 * s2, s2 * c2));
        }
    }
}

extern "C" void kernel_launch(void* const* d_in, const int* in_sizes, int n_in,
                              void* d_out, int out_size) {
    const float4* in = (const float4*)d_in[0];
    float4* out = (float4*)d_out;
    int n = in_sizes[0] / 4;                  // N rows
    int threads = 256;
    int rows_per_block = threads * 4;
    int blocks = (n + rows_per_block - 1) / rows_per_block;
    quantum_probs_final<<<blocks, threads>>>(in, out, n);
}